// round 8
// baseline (speedup 1.0000x reference)
#include <cuda_runtime.h>
#include <cuda_fp16.h>
#include <mma.h>
#include <cstdint>
#include <type_traits>

using namespace nvcuda;

#define N_NODES 100000
#define N_EDGES 3200000
#define IN_DIM  256
#define HID_DIM 128
#define OUT_DIM 64
#define M_PAD   100096          // 782 * 128, so WMMA stores need no tail guard

#define SCAN_BLK 1024
#define N_SCAN_BLOCKS ((N_NODES + SCAN_BLK - 1) / SCAN_BLK)   // 98

// ---------------- device scratch (static: no runtime allocation) -------------
__device__ int    g_is64;
__device__ int    g_ecnt[N_NODES];
__device__ float  g_dis[N_NODES];
__device__ int    g_rowptr[N_NODES + 1];
__device__ int    g_cur[N_NODES];
__device__ int    g_col[N_EDGES];
__device__ int    g_bsum[N_SCAN_BLOCKS];
__device__ int    g_bofs[N_SCAN_BLOCKS];
__device__ __half g_h[(size_t)M_PAD * HID_DIM];   // dis-scaled transform output
__device__ __half g_a[(size_t)M_PAD * HID_DIM];   // aggregation output (next GEMM input)

// ---------------- init: zero histogram + edge dtype detect --------------------
// int64 values < 2^17 -> every odd 32-bit word is 0; int32 -> odd words random.
__global__ void k_init(const int* __restrict__ ei32) {
    int i = blockIdx.x * blockDim.x + threadIdx.x;
    if (i < N_NODES) g_ecnt[i] = 0;
    if (blockIdx.x == 0) {
        __shared__ int nz;
        if (threadIdx.x == 0) nz = 0;
        __syncthreads();
        int idx = 2 * threadIdx.x + 1;
        if (threadIdx.x < 64 && ei32[idx] != 0) atomicAdd(&nz, 1);
        __syncthreads();
        if (threadIdx.x == 0) g_is64 = (nz == 0) ? 1 : 0;
    }
}

__device__ __forceinline__ void decode_edge(const void* ei, int e, int& s, int& d) {
    if (g_is64) {
        const long long* p = (const long long*)ei;
        s = (int)p[e];
        d = (int)p[N_EDGES + e];
    } else {
        const int* p = (const int*)ei;
        s = p[e];
        d = p[N_EDGES + e];
    }
}

// in-degree histogram (decode in-flight; no src/dst materialization)
__global__ void k_prep(const void* __restrict__ ei) {
    int e = blockIdx.x * blockDim.x + threadIdx.x;
    if (e >= N_EDGES) return;
    int s, d;
    decode_edge(ei, e, s, d);
    if ((unsigned)d < N_NODES) atomicAdd(&g_ecnt[d], 1);
}

// block-level exclusive scan (also emits dis = rsqrt(deg+1))
__global__ void k_scanA() {
    __shared__ int s[SCAN_BLK];
    int gid = blockIdx.x * SCAN_BLK + threadIdx.x;
    int v = (gid < N_NODES) ? g_ecnt[gid] : 0;
    if (gid < N_NODES) g_dis[gid] = rsqrtf((float)(v + 1));
    s[threadIdx.x] = v;
    __syncthreads();
    #pragma unroll
    for (int d = 1; d < SCAN_BLK; d <<= 1) {
        int t = (threadIdx.x >= d) ? s[threadIdx.x - d] : 0;
        __syncthreads();
        s[threadIdx.x] += t;
        __syncthreads();
    }
    if (gid < N_NODES) g_rowptr[gid] = s[threadIdx.x] - v;
    if (threadIdx.x == SCAN_BLK - 1) g_bsum[blockIdx.x] = s[SCAN_BLK - 1];
}

// scan of the 98 block partials: one block, shuffle scan (was 8.9us serial)
__global__ void k_scanB() {
    int t = threadIdx.x;                       // 0..127
    int lane = t & 31, w = t >> 5;
    int v = (t < N_SCAN_BLOCKS) ? g_bsum[t] : 0;
    int x = v;
    #pragma unroll
    for (int d = 1; d < 32; d <<= 1) {
        int y = __shfl_up_sync(0xFFFFFFFFu, x, d);
        if (lane >= d) x += y;
    }
    __shared__ int wsum[4];
    if (lane == 31) wsum[w] = x;
    __syncthreads();
    int offs = 0;
    #pragma unroll
    for (int i = 0; i < 4; i++) offs += (i < w) ? wsum[i] : 0;
    if (t < N_SCAN_BLOCKS) g_bofs[t] = offs + x - v;   // exclusive
}

__global__ void k_scanC() {
    int i = blockIdx.x * blockDim.x + threadIdx.x;
    if (i < N_NODES) {
        int r = g_rowptr[i] + g_bofs[i / SCAN_BLK];
        g_rowptr[i] = r;
        g_cur[i] = r;
    }
    if (i == 0) g_rowptr[N_NODES] = N_EDGES;
}

__global__ void k_scatter(const void* __restrict__ ei) {
    int e = blockIdx.x * blockDim.x + threadIdx.x;
    if (e < N_EDGES) {
        int src, dst;
        decode_edge(ei, e, src, dst);
        if ((unsigned)dst < N_NODES && (unsigned)src < N_NODES) {
            int pos = atomicAdd(&g_cur[dst], 1);
            g_col[pos] = src;
        }
    }
}

// ---------------- WMMA GEMM: C_half[r,:] = dis[r] * (A[r,:] @ B_f32) ----------
// A is fp32 (layer 1) or fp16 (layers 2,3); converted/scaled while staging.
// fp32 accum, fp16 output. BM=128, BK=32, 256 threads = 8 warps.
template <int BN, int WM, int WN, typename TA>
__global__ __launch_bounds__(256) void gemm_wmma(
    const TA* __restrict__ A, const float* __restrict__ B,
    __half* __restrict__ C, const float* __restrict__ dis, int M, int K)
{
    constexpr int BM = 128, BK = 32, PAD = 8;
    constexpr int WARPS_M = BM / WM;
    constexpr int MT = WM / 16, NT = WN / 16;
    static_assert((BM / WM) * (BN / WN) == 8, "8 warps");

    __shared__ __half As[BM][BK + PAD];
    __shared__ __half Bs[BK][BN + PAD];

    int tid = threadIdx.x;
    int warpId = tid >> 5;
    int wm = warpId % WARPS_M;
    int wn = warpId / WARPS_M;
    int row0 = blockIdx.x * BM;

    wmma::fragment<wmma::accumulator, 16, 16, 16, float> cf[MT][NT];
    #pragma unroll
    for (int i = 0; i < MT; i++)
        #pragma unroll
        for (int j = 0; j < NT; j++) wmma::fill_fragment(cf[i][j], 0.0f);

    for (int kt = 0; kt < K; kt += BK) {
        // stage A: 128 x 32 -> dis-scaled fp16 smem (4 elems per thread-iter)
        #pragma unroll
        for (int i = tid; i < BM * BK / 4; i += 256) {
            int r  = i >> 3;
            int c4 = (i & 7) << 2;
            float4 v = make_float4(0.f, 0.f, 0.f, 0.f);
            int grow = row0 + r;
            if (grow < M) {
                if constexpr (std::is_same<TA, float>::value) {
                    v = *(const float4*)&A[(size_t)grow * K + kt + c4];
                } else {
                    const __half2* p = (const __half2*)&A[(size_t)grow * K + kt + c4];
                    float2 u = __half22float2(p[0]);
                    float2 w2 = __half22float2(p[1]);
                    v = make_float4(u.x, u.y, w2.x, w2.y);
                }
                float w = __ldg(&dis[grow]);
                v.x *= w; v.y *= w; v.z *= w; v.w *= w;
            }
            As[r][c4 + 0] = __float2half_rn(v.x);
            As[r][c4 + 1] = __float2half_rn(v.y);
            As[r][c4 + 2] = __float2half_rn(v.z);
            As[r][c4 + 3] = __float2half_rn(v.w);
        }
        // stage B: 32 x BN fp32 -> fp16 smem
        #pragma unroll
        for (int i = tid; i < BK * BN / 4; i += 256) {
            int r  = i / (BN / 4);
            int c4 = (i % (BN / 4)) << 2;
            float4 v = *(const float4*)&B[(size_t)(kt + r) * BN + c4];
            Bs[r][c4 + 0] = __float2half_rn(v.x);
            Bs[r][c4 + 1] = __float2half_rn(v.y);
            Bs[r][c4 + 2] = __float2half_rn(v.z);
            Bs[r][c4 + 3] = __float2half_rn(v.w);
        }
        __syncthreads();

        #pragma unroll
        for (int kk = 0; kk < BK; kk += 16) {
            wmma::fragment<wmma::matrix_a, 16, 16, 16, __half, wmma::row_major> af[MT];
            wmma::fragment<wmma::matrix_b, 16, 16, 16, __half, wmma::row_major> bf[NT];
            #pragma unroll
            for (int i = 0; i < MT; i++)
                wmma::load_matrix_sync(af[i], &As[wm * WM + i * 16][kk], BK + PAD);
            #pragma unroll
            for (int j = 0; j < NT; j++)
                wmma::load_matrix_sync(bf[j], &Bs[kk][wn * WN + j * 16], BN + PAD);
            #pragma unroll
            for (int i = 0; i < MT; i++)
                #pragma unroll
                for (int j = 0; j < NT; j++)
                    wmma::mma_sync(cf[i][j], af[i], bf[j], cf[i][j]);
        }
        __syncthreads();
    }

    #pragma unroll
    for (int i = 0; i < MT; i++) {
        #pragma unroll
        for (int j = 0; j < NT; j++) {
            wmma::fragment<wmma::accumulator, 16, 16, 16, __half> hf;
            #pragma unroll
            for (int e = 0; e < cf[i][j].num_elements; e++)
                hf.x[e] = __float2half_rn(cf[i][j].x[e]);
            __half* dst = C + (size_t)(row0 + wm * WM + i * 16) * BN + wn * WN + j * 16;
            wmma::store_matrix_sync(dst, hf, BN, wmma::mem_row_major);
        }
    }
}

// ---------------- aggregation --------------------------------------------------
// h' rows are pre-scaled by dis[src]. out[i] = dis[i]*(h'_i + sum_j h'_j) + b.
// GROUP lanes per dst node; each lane owns 4 fp16 features (8B loads).
// TOUT=__half for intermediate layers (next GEMM stages fp16 anyway: identical
// rounding, half the traffic); TOUT=float for the final layer (d_out).
template <int F, int GROUP, bool RELU, typename TOUT>
__global__ __launch_bounds__(256) void agg_kernel(
    const __half* __restrict__ h, TOUT* __restrict__ out,
    const float* __restrict__ bias)
{
    static_assert(F == GROUP * 4, "lane owns 4 features");
    int gtid = blockIdx.x * blockDim.x + threadIdx.x;
    int node = gtid / GROUP;
    int lane = gtid % GROUP;
    if (node >= N_NODES) return;

    // self term (h' already dis-scaled)
    const __half2* ps = (const __half2*)(h + (size_t)node * F + lane * 4);
    float2 su = __half22float2(ps[0]);
    float2 sv = __half22float2(ps[1]);
    float4 acc = make_float4(su.x, su.y, sv.x, sv.y);

    int p   = g_rowptr[node];
    int end = g_rowptr[node + 1];

    for (; p + 4 <= end; p += 4) {
        int j0 = __ldg(&g_col[p + 0]);
        int j1 = __ldg(&g_col[p + 1]);
        int j2 = __ldg(&g_col[p + 2]);
        int j3 = __ldg(&g_col[p + 3]);
        const __half2* q0 = (const __half2*)(h + (size_t)j0 * F + lane * 4);
        const __half2* q1 = (const __half2*)(h + (size_t)j1 * F + lane * 4);
        const __half2* q2 = (const __half2*)(h + (size_t)j2 * F + lane * 4);
        const __half2* q3 = (const __half2*)(h + (size_t)j3 * F + lane * 4);
        float2 a0 = __half22float2(q0[0]), b0 = __half22float2(q0[1]);
        float2 a1 = __half22float2(q1[0]), b1 = __half22float2(q1[1]);
        float2 a2 = __half22float2(q2[0]), b2 = __half22float2(q2[1]);
        float2 a3 = __half22float2(q3[0]), b3 = __half22float2(q3[1]);
        acc.x += (a0.x + a1.x) + (a2.x + a3.x);
        acc.y += (a0.y + a1.y) + (a2.y + a3.y);
        acc.z += (b0.x + b1.x) + (b2.x + b3.x);
        acc.w += (b0.y + b1.y) + (b2.y + b3.y);
    }
    for (; p < end; p++) {
        int j = __ldg(&g_col[p]);
        const __half2* q = (const __half2*)(h + (size_t)j * F + lane * 4);
        float2 u = __half22float2(q[0]);
        float2 v = __half22float2(q[1]);
        acc.x += u.x; acc.y += u.y; acc.z += v.x; acc.w += v.y;
    }

    float di = __ldg(&g_dis[node]);
    float4 b4 = *(const float4*)&bias[lane * 4];
    float4 o;
    o.x = di * acc.x + b4.x;
    o.y = di * acc.y + b4.y;
    o.z = di * acc.z + b4.z;
    o.w = di * acc.w + b4.w;
    if (RELU) {
        o.x = fmaxf(o.x, 0.f); o.y = fmaxf(o.y, 0.f);
        o.z = fmaxf(o.z, 0.f); o.w = fmaxf(o.w, 0.f);
    }
    if constexpr (std::is_same<TOUT, float>::value) {
        *(float4*)&out[(size_t)node * F + lane * 4] = o;
    } else {
        __half2* po = (__half2*)(out + (size_t)node * F + lane * 4);
        po[0] = __floats2half2_rn(o.x, o.y);
        po[1] = __floats2half2_rn(o.z, o.w);
    }
}

// ---------------- launch ------------------------------------------------------
extern "C" void kernel_launch(void* const* d_in, const int* in_sizes, int n_in,
                              void* d_out, int out_size)
{
    const float* x  = (const float*)d_in[0];
    const void*  ei = d_in[1];
    const float* W1 = (const float*)d_in[2];
    const float* b1 = (const float*)d_in[3];
    const float* W2 = (const float*)d_in[4];
    const float* b2 = (const float*)d_in[5];
    const float* W3 = (const float*)d_in[6];
    const float* b3 = (const float*)d_in[7];
    float* out = (float*)d_out;

    __half* hbuf = nullptr;
    __half* abuf = nullptr;
    float*  disb = nullptr;
    cudaGetSymbolAddress((void**)&hbuf, g_h);
    cudaGetSymbolAddress((void**)&abuf, g_a);
    cudaGetSymbolAddress((void**)&disb, g_dis);

    const int TPB = 256;
    int nb_nodes = (N_NODES + TPB - 1) / TPB;
    int nb_edges = (N_EDGES + TPB - 1) / TPB;

    // --- CSR build ---
    k_init<<<nb_nodes, TPB>>>((const int*)ei);
    k_prep<<<nb_edges, TPB>>>(ei);
    k_scanA<<<N_SCAN_BLOCKS, SCAN_BLK>>>();
    k_scanB<<<1, 128>>>();
    k_scanC<<<nb_nodes, TPB>>>();
    k_scatter<<<nb_edges, TPB>>>(ei);

    int gemm_blocks = (N_NODES + 127) / 128;                 // 782
    int agg_blocks_128 = (N_NODES * 32 + TPB - 1) / TPB;     // GROUP=32
    int agg_blocks_64  = (N_NODES * 16 + TPB - 1) / TPB;     // GROUP=16

    // --- layer 1: h' = dis*(x @ W1) -> agg+relu -> a (fp16)
    gemm_wmma<128, 64, 32><<<gemm_blocks, 256>>>(x, W1, hbuf, disb, N_NODES, IN_DIM);
    agg_kernel<128, 32, true, __half><<<agg_blocks_128, 256>>>(hbuf, abuf, b1);

    // --- layer 2: h' = dis*(a @ W2) -> agg+relu -> a (fp16)
    gemm_wmma<128, 64, 32><<<gemm_blocks, 256>>>(abuf, W2, hbuf, disb, N_NODES, HID_DIM);
    agg_kernel<128, 32, true, __half><<<agg_blocks_128, 256>>>(hbuf, abuf, b2);

    // --- layer 3: h' = dis*(a @ W3) -> agg (no relu) -> d_out (fp32)
    gemm_wmma<64, 32, 32><<<gemm_blocks, 256>>>(abuf, W3, hbuf, disb, N_NODES, HID_DIM);
    agg_kernel<64, 16, false, float><<<agg_blocks_64, 256>>>(hbuf, out, b3);
}

// round 9
// speedup vs baseline: 1.3679x; 1.3679x over previous
#include <cuda_runtime.h>
#include <cuda_fp16.h>
#include <mma.h>
#include <cstdint>

using namespace nvcuda;

#define N_NODES 100000
#define N_EDGES 3200000
#define IN_DIM  256
#define HID_DIM 128
#define OUT_DIM 64
#define M_PAD   100096          // 782 * 128, so WMMA stores need no tail guard

#define SCAN_BLK 1024
#define N_SCAN_BLOCKS ((N_NODES + SCAN_BLK - 1) / SCAN_BLK)   // 98

// ---------------- device scratch (static: no runtime allocation) -------------
__device__ int    g_is64;
__device__ int    g_src[N_EDGES];
__device__ int    g_dst[N_EDGES];
__device__ int    g_ecnt[N_NODES];
__device__ float  g_dis[N_NODES];
__device__ int    g_rowptr[N_NODES + 1];
__device__ int    g_cur[N_NODES];
__device__ int    g_col[N_EDGES];
__device__ int    g_bsum[N_SCAN_BLOCKS];
__device__ int    g_bofs[N_SCAN_BLOCKS];
__device__ __half g_h[(size_t)M_PAD * HID_DIM];   // dis-scaled transform output, fp16
__device__ float  g_a[(size_t)M_PAD * HID_DIM];   // aggregation output (GEMM input), fp32

// ---------------- init: zero histogram + edge dtype detect --------------------
// int64 values < 2^17 -> every odd 32-bit word is 0; int32 -> odd words random.
__global__ void k_init(const int* __restrict__ ei32) {
    int i = blockIdx.x * blockDim.x + threadIdx.x;
    if (i < N_NODES) g_ecnt[i] = 0;
    if (blockIdx.x == 0) {
        __shared__ int nz;
        if (threadIdx.x == 0) nz = 0;
        __syncthreads();
        int idx = 2 * threadIdx.x + 1;
        if (threadIdx.x < 64 && ei32[idx] != 0) atomicAdd(&nz, 1);
        __syncthreads();
        if (threadIdx.x == 0) g_is64 = (nz == 0) ? 1 : 0;
    }
}

// fused: normalize edge dtype + in-degree histogram (one pass over edge_index)
__global__ void k_prep(const void* __restrict__ ei) {
    int e = blockIdx.x * blockDim.x + threadIdx.x;
    if (e >= N_EDGES) return;
    int s, d;
    if (g_is64) {
        const long long* p = (const long long*)ei;
        s = (int)p[e];
        d = (int)p[N_EDGES + e];
    } else {
        const int* p = (const int*)ei;
        s = p[e];
        d = p[N_EDGES + e];
    }
    g_src[e] = s;
    g_dst[e] = d;
    if ((unsigned)d < N_NODES) atomicAdd(&g_ecnt[d], 1);
}

// block-level exclusive scan (also emits dis = rsqrt(deg+1))
__global__ void k_scanA() {
    __shared__ int s[SCAN_BLK];
    int gid = blockIdx.x * SCAN_BLK + threadIdx.x;
    int v = (gid < N_NODES) ? g_ecnt[gid] : 0;
    if (gid < N_NODES) g_dis[gid] = rsqrtf((float)(v + 1));
    s[threadIdx.x] = v;
    __syncthreads();
    #pragma unroll
    for (int d = 1; d < SCAN_BLK; d <<= 1) {
        int t = (threadIdx.x >= d) ? s[threadIdx.x - d] : 0;
        __syncthreads();
        s[threadIdx.x] += t;
        __syncthreads();
    }
    if (gid < N_NODES) g_rowptr[gid] = s[threadIdx.x] - v;
    if (threadIdx.x == SCAN_BLK - 1) g_bsum[blockIdx.x] = s[SCAN_BLK - 1];
}

// scan of the 98 block partials: one block, shuffle scan (was 8.9us serial)
__global__ void k_scanB() {
    int t = threadIdx.x;                       // 0..127
    int lane = t & 31, w = t >> 5;
    int v = (t < N_SCAN_BLOCKS) ? g_bsum[t] : 0;
    int x = v;
    #pragma unroll
    for (int d = 1; d < 32; d <<= 1) {
        int y = __shfl_up_sync(0xFFFFFFFFu, x, d);
        if (lane >= d) x += y;
    }
    __shared__ int wsum[4];
    if (lane == 31) wsum[w] = x;
    __syncthreads();
    int offs = 0;
    #pragma unroll
    for (int i = 0; i < 4; i++) offs += (i < w) ? wsum[i] : 0;
    if (t < N_SCAN_BLOCKS) g_bofs[t] = offs + x - v;   // exclusive
}

__global__ void k_scanC() {
    int i = blockIdx.x * blockDim.x + threadIdx.x;
    if (i < N_NODES) {
        int r = g_rowptr[i] + g_bofs[i / SCAN_BLK];
        g_rowptr[i] = r;
        g_cur[i] = r;
    }
    if (i == 0) g_rowptr[N_NODES] = N_EDGES;
}

__global__ void k_scatter() {
    int e = blockIdx.x * blockDim.x + threadIdx.x;
    if (e < N_EDGES) {
        int src = g_src[e];
        int dst = g_dst[e];
        if ((unsigned)dst < N_NODES && (unsigned)src < N_NODES) {
            int pos = atomicAdd(&g_cur[dst], 1);
            g_col[pos] = src;
        }
    }
}

// ---------------- WMMA GEMM: C_half[r,:] = dis[r] * (A[r,:] @ B) --------------
// dis-scaling folded into the A staging (dis[r]*A_row). fp32->fp16 on stage,
// fp32 accum, fp16 output. BM=128, BK=32, 256 threads = 8 warps.
template <int BN, int WM, int WN>
__global__ __launch_bounds__(256) void gemm_wmma(
    const float* __restrict__ A, const float* __restrict__ B,
    __half* __restrict__ C, const float* __restrict__ dis, int M, int K)
{
    constexpr int BM = 128, BK = 32, PAD = 8;
    constexpr int WARPS_M = BM / WM;
    constexpr int MT = WM / 16, NT = WN / 16;
    static_assert((BM / WM) * (BN / WN) == 8, "8 warps");

    __shared__ __half As[BM][BK + PAD];
    __shared__ __half Bs[BK][BN + PAD];

    int tid = threadIdx.x;
    int warpId = tid >> 5;
    int wm = warpId % WARPS_M;
    int wn = warpId / WARPS_M;
    int row0 = blockIdx.x * BM;

    wmma::fragment<wmma::accumulator, 16, 16, 16, float> cf[MT][NT];
    #pragma unroll
    for (int i = 0; i < MT; i++)
        #pragma unroll
        for (int j = 0; j < NT; j++) wmma::fill_fragment(cf[i][j], 0.0f);

    for (int kt = 0; kt < K; kt += BK) {
        // stage A: 128 x 32 fp32 -> dis-scaled fp16 smem (float4 loads)
        #pragma unroll
        for (int i = tid; i < BM * BK / 4; i += 256) {
            int r  = i >> 3;
            int c4 = (i & 7) << 2;
            float4 v = make_float4(0.f, 0.f, 0.f, 0.f);
            int grow = row0 + r;
            if (grow < M) {
                v = *(const float4*)&A[(size_t)grow * K + kt + c4];
                float w = __ldg(&dis[grow]);
                v.x *= w; v.y *= w; v.z *= w; v.w *= w;
            }
            As[r][c4 + 0] = __float2half_rn(v.x);
            As[r][c4 + 1] = __float2half_rn(v.y);
            As[r][c4 + 2] = __float2half_rn(v.z);
            As[r][c4 + 3] = __float2half_rn(v.w);
        }
        // stage B: 32 x BN fp32 -> fp16 smem
        #pragma unroll
        for (int i = tid; i < BK * BN / 4; i += 256) {
            int r  = i / (BN / 4);
            int c4 = (i % (BN / 4)) << 2;
            float4 v = *(const float4*)&B[(size_t)(kt + r) * BN + c4];
            Bs[r][c4 + 0] = __float2half_rn(v.x);
            Bs[r][c4 + 1] = __float2half_rn(v.y);
            Bs[r][c4 + 2] = __float2half_rn(v.z);
            Bs[r][c4 + 3] = __float2half_rn(v.w);
        }
        __syncthreads();

        #pragma unroll
        for (int kk = 0; kk < BK; kk += 16) {
            wmma::fragment<wmma::matrix_a, 16, 16, 16, __half, wmma::row_major> af[MT];
            wmma::fragment<wmma::matrix_b, 16, 16, 16, __half, wmma::row_major> bf[NT];
            #pragma unroll
            for (int i = 0; i < MT; i++)
                wmma::load_matrix_sync(af[i], &As[wm * WM + i * 16][kk], BK + PAD);
            #pragma unroll
            for (int j = 0; j < NT; j++)
                wmma::load_matrix_sync(bf[j], &Bs[kk][wn * WN + j * 16], BN + PAD);
            #pragma unroll
            for (int i = 0; i < MT; i++)
                #pragma unroll
                for (int j = 0; j < NT; j++)
                    wmma::mma_sync(cf[i][j], af[i], bf[j], cf[i][j]);
        }
        __syncthreads();
    }

    #pragma unroll
    for (int i = 0; i < MT; i++) {
        #pragma unroll
        for (int j = 0; j < NT; j++) {
            wmma::fragment<wmma::accumulator, 16, 16, 16, __half> hf;
            #pragma unroll
            for (int e = 0; e < cf[i][j].num_elements; e++)
                hf.x[e] = __float2half_rn(cf[i][j].x[e]);
            __half* dst = C + (size_t)(row0 + wm * WM + i * 16) * BN + wn * WN + j * 16;
            wmma::store_matrix_sync(dst, hf, BN, wmma::mem_row_major);
        }
    }
}

// ---------------- aggregation --------------------------------------------------
// h' rows are pre-scaled by dis[src]. out[i] = dis[i]*(h'_i + sum_j h'_j) + b.
// GROUP lanes cooperate on one dst node; each lane owns 4 fp16 features (8B).
// GROUP=32 for F=128, GROUP=16 for F=64 (2 nodes per warp).
template <int F, int GROUP, bool RELU>
__global__ __launch_bounds__(256) void agg_kernel(
    const __half* __restrict__ h, float* __restrict__ out,
    const float* __restrict__ bias)
{
    static_assert(F == GROUP * 4, "lane owns 4 features");
    int gtid = blockIdx.x * blockDim.x + threadIdx.x;
    int node = gtid / GROUP;
    int lane = gtid % GROUP;
    if (node >= N_NODES) return;

    // self term (h' already dis-scaled)
    const __half2* ps = (const __half2*)(h + (size_t)node * F + lane * 4);
    float2 su = __half22float2(ps[0]);
    float2 sv = __half22float2(ps[1]);
    float4 acc = make_float4(su.x, su.y, sv.x, sv.y);

    int p   = g_rowptr[node];
    int end = g_rowptr[node + 1];

    for (; p + 4 <= end; p += 4) {
        int j0 = __ldg(&g_col[p + 0]);
        int j1 = __ldg(&g_col[p + 1]);
        int j2 = __ldg(&g_col[p + 2]);
        int j3 = __ldg(&g_col[p + 3]);
        const __half2* q0 = (const __half2*)(h + (size_t)j0 * F + lane * 4);
        const __half2* q1 = (const __half2*)(h + (size_t)j1 * F + lane * 4);
        const __half2* q2 = (const __half2*)(h + (size_t)j2 * F + lane * 4);
        const __half2* q3 = (const __half2*)(h + (size_t)j3 * F + lane * 4);
        float2 a0 = __half22float2(q0[0]), b0 = __half22float2(q0[1]);
        float2 a1 = __half22float2(q1[0]), b1 = __half22float2(q1[1]);
        float2 a2 = __half22float2(q2[0]), b2 = __half22float2(q2[1]);
        float2 a3 = __half22float2(q3[0]), b3 = __half22float2(q3[1]);
        acc.x += (a0.x + a1.x) + (a2.x + a3.x);
        acc.y += (a0.y + a1.y) + (a2.y + a3.y);
        acc.z += (b0.x + b1.x) + (b2.x + b3.x);
        acc.w += (b0.y + b1.y) + (b2.y + b3.y);
    }
    for (; p < end; p++) {
        int j = __ldg(&g_col[p]);
        const __half2* q = (const __half2*)(h + (size_t)j * F + lane * 4);
        float2 u = __half22float2(q[0]);
        float2 v = __half22float2(q[1]);
        acc.x += u.x; acc.y += u.y; acc.z += v.x; acc.w += v.y;
    }

    float di = __ldg(&g_dis[node]);
    float4 b4 = *(const float4*)&bias[lane * 4];
    float4 o;
    o.x = di * acc.x + b4.x;
    o.y = di * acc.y + b4.y;
    o.z = di * acc.z + b4.z;
    o.w = di * acc.w + b4.w;
    if (RELU) {
        o.x = fmaxf(o.x, 0.f); o.y = fmaxf(o.y, 0.f);
        o.z = fmaxf(o.z, 0.f); o.w = fmaxf(o.w, 0.f);
    }
    *(float4*)&out[(size_t)node * F + lane * 4] = o;
}

// ---------------- launch ------------------------------------------------------
extern "C" void kernel_launch(void* const* d_in, const int* in_sizes, int n_in,
                              void* d_out, int out_size)
{
    const float* x  = (const float*)d_in[0];
    const void*  ei = d_in[1];
    const float* W1 = (const float*)d_in[2];
    const float* b1 = (const float*)d_in[3];
    const float* W2 = (const float*)d_in[4];
    const float* b2 = (const float*)d_in[5];
    const float* W3 = (const float*)d_in[6];
    const float* b3 = (const float*)d_in[7];
    float* out = (float*)d_out;

    __half* hbuf = nullptr;
    float*  abuf = nullptr;
    float*  disb = nullptr;
    cudaGetSymbolAddress((void**)&hbuf, g_h);
    cudaGetSymbolAddress((void**)&abuf, g_a);
    cudaGetSymbolAddress((void**)&disb, g_dis);

    const int TPB = 256;
    int nb_nodes = (N_NODES + TPB - 1) / TPB;
    int nb_edges = (N_EDGES + TPB - 1) / TPB;

    // --- CSR build (6 launches) ---
    k_init<<<nb_nodes, TPB>>>((const int*)ei);
    k_prep<<<nb_edges, TPB>>>(ei);
    k_scanA<<<N_SCAN_BLOCKS, SCAN_BLK>>>();
    k_scanB<<<1, 128>>>();
    k_scanC<<<nb_nodes, TPB>>>();
    k_scatter<<<nb_edges, TPB>>>();

    int gemm_blocks = (N_NODES + 127) / 128;                 // 782
    int agg_blocks_128 = (N_NODES * 32 + TPB - 1) / TPB;     // GROUP=32
    int agg_blocks_64  = (N_NODES * 16 + TPB - 1) / TPB;     // GROUP=16

    // --- layer 1: h' = dis*(x @ W1) -> agg+relu -> a
    gemm_wmma<128, 64, 32><<<gemm_blocks, 256>>>(x, W1, hbuf, disb, N_NODES, IN_DIM);
    agg_kernel<128, 32, true><<<agg_blocks_128, 256>>>(hbuf, abuf, b1);

    // --- layer 2: h' = dis*(a @ W2) -> agg+relu -> a
    gemm_wmma<128, 64, 32><<<gemm_blocks, 256>>>(abuf, W2, hbuf, disb, N_NODES, HID_DIM);
    agg_kernel<128, 32, true><<<agg_blocks_128, 256>>>(hbuf, abuf, b2);

    // --- layer 3: h' = dis*(a @ W3) -> agg (no relu) -> d_out
    gemm_wmma<64, 32, 32><<<gemm_blocks, 256>>>(abuf, W3, hbuf, disb, N_NODES, HID_DIM);
    agg_kernel<64, 16, false><<<agg_blocks_64, 256>>>(hbuf, out, b3);
}

// round 10
// speedup vs baseline: 1.4845x; 1.0853x over previous
#include <cuda_runtime.h>
#include <cuda_fp16.h>
#include <mma.h>
#include <cstdint>

using namespace nvcuda;

#define N_NODES 100000
#define N_EDGES 3200000
#define IN_DIM  256
#define HID_DIM 128
#define OUT_DIM 64
#define M_PAD   100096          // 782 * 128, so WMMA stores need no tail guard

#define SCAN_BLK 1024
#define N_SCAN_BLOCKS ((N_NODES + SCAN_BLK - 1) / SCAN_BLK)   // 98

// ---------------- device scratch (static: no runtime allocation) -------------
__device__ int    g_is64;
__device__ int    g_src[N_EDGES];
__device__ int    g_dst[N_EDGES];
__device__ int    g_ecnt[N_NODES];
__device__ float  g_dis[N_NODES];
__device__ int    g_rowptr[N_NODES + 1];
__device__ int    g_cur[N_NODES];
__device__ int    g_col[N_EDGES];
__device__ int    g_bsum[N_SCAN_BLOCKS];
__device__ int    g_bofs[N_SCAN_BLOCKS];
__device__ __half g_h[(size_t)M_PAD * HID_DIM];   // dis-scaled transform output, fp16
__device__ float  g_a[(size_t)M_PAD * HID_DIM];   // aggregation output (GEMM input), fp32

// ---------------- init: zero histogram + edge dtype detect --------------------
// int64 values < 2^17 -> every odd 32-bit word is 0; int32 -> odd words random.
__global__ void k_init(const int* __restrict__ ei32) {
    int i = blockIdx.x * blockDim.x + threadIdx.x;
    if (i < N_NODES) g_ecnt[i] = 0;
    if (blockIdx.x == 0) {
        __shared__ int nz;
        if (threadIdx.x == 0) nz = 0;
        __syncthreads();
        int idx = 2 * threadIdx.x + 1;
        if (threadIdx.x < 64 && ei32[idx] != 0) atomicAdd(&nz, 1);
        __syncthreads();
        if (threadIdx.x == 0) g_is64 = (nz == 0) ? 1 : 0;
    }
}

// fused: normalize edge dtype + in-degree histogram (one pass over edge_index)
__global__ void k_prep(const void* __restrict__ ei) {
    int e = blockIdx.x * blockDim.x + threadIdx.x;
    if (e >= N_EDGES) return;
    int s, d;
    if (g_is64) {
        const long long* p = (const long long*)ei;
        s = (int)p[e];
        d = (int)p[N_EDGES + e];
    } else {
        const int* p = (const int*)ei;
        s = p[e];
        d = p[N_EDGES + e];
    }
    g_src[e] = s;
    g_dst[e] = d;
    if ((unsigned)d < N_NODES) atomicAdd(&g_ecnt[d], 1);
}

// block-level exclusive scan (also emits dis = rsqrt(deg+1))
__global__ void k_scanA() {
    __shared__ int s[SCAN_BLK];
    int gid = blockIdx.x * SCAN_BLK + threadIdx.x;
    int v = (gid < N_NODES) ? g_ecnt[gid] : 0;
    if (gid < N_NODES) g_dis[gid] = rsqrtf((float)(v + 1));
    s[threadIdx.x] = v;
    __syncthreads();
    #pragma unroll
    for (int d = 1; d < SCAN_BLK; d <<= 1) {
        int t = (threadIdx.x >= d) ? s[threadIdx.x - d] : 0;
        __syncthreads();
        s[threadIdx.x] += t;
        __syncthreads();
    }
    if (gid < N_NODES) g_rowptr[gid] = s[threadIdx.x] - v;
    if (threadIdx.x == SCAN_BLK - 1) g_bsum[blockIdx.x] = s[SCAN_BLK - 1];
}

// scan of the 98 block partials: one block, shuffle scan
__global__ void k_scanB() {
    int t = threadIdx.x;                       // 0..127
    int lane = t & 31, w = t >> 5;
    int v = (t < N_SCAN_BLOCKS) ? g_bsum[t] : 0;
    int x = v;
    #pragma unroll
    for (int d = 1; d < 32; d <<= 1) {
        int y = __shfl_up_sync(0xFFFFFFFFu, x, d);
        if (lane >= d) x += y;
    }
    __shared__ int wsum[4];
    if (lane == 31) wsum[w] = x;
    __syncthreads();
    int offs = 0;
    #pragma unroll
    for (int i = 0; i < 4; i++) offs += (i < w) ? wsum[i] : 0;
    if (t < N_SCAN_BLOCKS) g_bofs[t] = offs + x - v;   // exclusive
}

__global__ void k_scanC() {
    int i = blockIdx.x * blockDim.x + threadIdx.x;
    if (i < N_NODES) {
        int r = g_rowptr[i] + g_bofs[i / SCAN_BLK];
        g_rowptr[i] = r;
        g_cur[i] = r;
    }
    if (i == 0) g_rowptr[N_NODES] = N_EDGES;
}

__global__ void k_scatter() {
    int e = blockIdx.x * blockDim.x + threadIdx.x;
    if (e < N_EDGES) {
        int src = g_src[e];
        int dst = g_dst[e];
        if ((unsigned)dst < N_NODES && (unsigned)src < N_NODES) {
            int pos = atomicAdd(&g_cur[dst], 1);
            g_col[pos] = src;
        }
    }
}

// ---------------- WMMA GEMM: C_half[r,:] = dis[r] * (A[r,:] @ B) --------------
// dis-scaling folded into the A staging (dis[r]*A_row). fp32->fp16 on stage,
// fp32 accum, fp16 output. BM=128, BK=32, 256 threads = 8 warps.
template <int BN, int WM, int WN>
__global__ __launch_bounds__(256) void gemm_wmma(
    const float* __restrict__ A, const float* __restrict__ B,
    __half* __restrict__ C, const float* __restrict__ dis, int M, int K)
{
    constexpr int BM = 128, BK = 32, PAD = 8;
    constexpr int WARPS_M = BM / WM;
    constexpr int MT = WM / 16, NT = WN / 16;
    static_assert((BM / WM) * (BN / WN) == 8, "8 warps");

    __shared__ __half As[BM][BK + PAD];
    __shared__ __half Bs[BK][BN + PAD];

    int tid = threadIdx.x;
    int warpId = tid >> 5;
    int wm = warpId % WARPS_M;
    int wn = warpId / WARPS_M;
    int row0 = blockIdx.x * BM;

    wmma::fragment<wmma::accumulator, 16, 16, 16, float> cf[MT][NT];
    #pragma unroll
    for (int i = 0; i < MT; i++)
        #pragma unroll
        for (int j = 0; j < NT; j++) wmma::fill_fragment(cf[i][j], 0.0f);

    for (int kt = 0; kt < K; kt += BK) {
        // stage A: 128 x 32 fp32 -> dis-scaled fp16 smem (float4 loads)
        #pragma unroll
        for (int i = tid; i < BM * BK / 4; i += 256) {
            int r  = i >> 3;
            int c4 = (i & 7) << 2;
            float4 v = make_float4(0.f, 0.f, 0.f, 0.f);
            int grow = row0 + r;
            if (grow < M) {
                v = *(const float4*)&A[(size_t)grow * K + kt + c4];
                float w = __ldg(&dis[grow]);
                v.x *= w; v.y *= w; v.z *= w; v.w *= w;
            }
            As[r][c4 + 0] = __float2half_rn(v.x);
            As[r][c4 + 1] = __float2half_rn(v.y);
            As[r][c4 + 2] = __float2half_rn(v.z);
            As[r][c4 + 3] = __float2half_rn(v.w);
        }
        // stage B: 32 x BN fp32 -> fp16 smem
        #pragma unroll
        for (int i = tid; i < BK * BN / 4; i += 256) {
            int r  = i / (BN / 4);
            int c4 = (i % (BN / 4)) << 2;
            float4 v = *(const float4*)&B[(size_t)(kt + r) * BN + c4];
            Bs[r][c4 + 0] = __float2half_rn(v.x);
            Bs[r][c4 + 1] = __float2half_rn(v.y);
            Bs[r][c4 + 2] = __float2half_rn(v.z);
            Bs[r][c4 + 3] = __float2half_rn(v.w);
        }
        __syncthreads();

        #pragma unroll
        for (int kk = 0; kk < BK; kk += 16) {
            wmma::fragment<wmma::matrix_a, 16, 16, 16, __half, wmma::row_major> af[MT];
            wmma::fragment<wmma::matrix_b, 16, 16, 16, __half, wmma::row_major> bf[NT];
            #pragma unroll
            for (int i = 0; i < MT; i++)
                wmma::load_matrix_sync(af[i], &As[wm * WM + i * 16][kk], BK + PAD);
            #pragma unroll
            for (int j = 0; j < NT; j++)
                wmma::load_matrix_sync(bf[j], &Bs[kk][wn * WN + j * 16], BN + PAD);
            #pragma unroll
            for (int i = 0; i < MT; i++)
                #pragma unroll
                for (int j = 0; j < NT; j++)
                    wmma::mma_sync(cf[i][j], af[i], bf[j], cf[i][j]);
        }
        __syncthreads();
    }

    #pragma unroll
    for (int i = 0; i < MT; i++) {
        #pragma unroll
        for (int j = 0; j < NT; j++) {
            wmma::fragment<wmma::accumulator, 16, 16, 16, __half> hf;
            #pragma unroll
            for (int e = 0; e < cf[i][j].num_elements; e++)
                hf.x[e] = __float2half_rn(cf[i][j].x[e]);
            __half* dst = C + (size_t)(row0 + wm * WM + i * 16) * BN + wn * WN + j * 16;
            wmma::store_matrix_sync(dst, hf, BN, wmma::mem_row_major);
        }
    }
}

// ---------------- aggregation --------------------------------------------------
// h' rows are pre-scaled by dis[src]. out[i] = dis[i]*(h'_i + sum_j h'_j) + b.
// GROUP lanes per dst node; each lane owns 8 fp16 features = ONE 16B LDG.128
// per gathered row (halves load-instruction count vs 8B lanes).
// GROUP=16 for F=128 (2 nodes/warp), GROUP=8 for F=64 (4 nodes/warp).
__device__ __forceinline__ void h8_acc(uint4 raw, float* f) {
    float2 u0 = __half22float2(*(__half2*)&raw.x);
    float2 u1 = __half22float2(*(__half2*)&raw.y);
    float2 u2 = __half22float2(*(__half2*)&raw.z);
    float2 u3 = __half22float2(*(__half2*)&raw.w);
    f[0] += u0.x; f[1] += u0.y; f[2] += u1.x; f[3] += u1.y;
    f[4] += u2.x; f[5] += u2.y; f[6] += u3.x; f[7] += u3.y;
}

template <int F, int GROUP, bool RELU>
__global__ __launch_bounds__(256) void agg_kernel(
    const __half* __restrict__ h, float* __restrict__ out,
    const float* __restrict__ bias)
{
    static_assert(F == GROUP * 8, "lane owns 8 features (16B)");
    constexpr int ROWU4 = F / 8;          // uint4 per row
    int gtid = blockIdx.x * blockDim.x + threadIdx.x;
    int node = gtid / GROUP;
    int lane = gtid % GROUP;
    if (node >= N_NODES) return;

    const uint4* h4 = (const uint4*)h;

    float acc[8] = {0.f, 0.f, 0.f, 0.f, 0.f, 0.f, 0.f, 0.f};
    // self term (h' already dis-scaled)
    h8_acc(__ldg(&h4[(size_t)node * ROWU4 + lane]), acc);

    int p   = g_rowptr[node];
    int end = g_rowptr[node + 1];

    for (; p + 4 <= end; p += 4) {
        int j0 = __ldg(&g_col[p + 0]);
        int j1 = __ldg(&g_col[p + 1]);
        int j2 = __ldg(&g_col[p + 2]);
        int j3 = __ldg(&g_col[p + 3]);
        uint4 r0 = __ldg(&h4[(size_t)j0 * ROWU4 + lane]);
        uint4 r1 = __ldg(&h4[(size_t)j1 * ROWU4 + lane]);
        uint4 r2 = __ldg(&h4[(size_t)j2 * ROWU4 + lane]);
        uint4 r3 = __ldg(&h4[(size_t)j3 * ROWU4 + lane]);
        h8_acc(r0, acc);
        h8_acc(r1, acc);
        h8_acc(r2, acc);
        h8_acc(r3, acc);
    }
    for (; p < end; p++) {
        int j = __ldg(&g_col[p]);
        h8_acc(__ldg(&h4[(size_t)j * ROWU4 + lane]), acc);
    }

    float di = __ldg(&g_dis[node]);
    float4 bA = *(const float4*)&bias[lane * 8 + 0];
    float4 bB = *(const float4*)&bias[lane * 8 + 4];
    float4 oA, oB;
    oA.x = di * acc[0] + bA.x; oA.y = di * acc[1] + bA.y;
    oA.z = di * acc[2] + bA.z; oA.w = di * acc[3] + bA.w;
    oB.x = di * acc[4] + bB.x; oB.y = di * acc[5] + bB.y;
    oB.z = di * acc[6] + bB.z; oB.w = di * acc[7] + bB.w;
    if (RELU) {
        oA.x = fmaxf(oA.x, 0.f); oA.y = fmaxf(oA.y, 0.f);
        oA.z = fmaxf(oA.z, 0.f); oA.w = fmaxf(oA.w, 0.f);
        oB.x = fmaxf(oB.x, 0.f); oB.y = fmaxf(oB.y, 0.f);
        oB.z = fmaxf(oB.z, 0.f); oB.w = fmaxf(oB.w, 0.f);
    }
    float* orow = &out[(size_t)node * F + lane * 8];
    *(float4*)&orow[0] = oA;
    *(float4*)&orow[4] = oB;
}

// ---------------- launch ------------------------------------------------------
extern "C" void kernel_launch(void* const* d_in, const int* in_sizes, int n_in,
                              void* d_out, int out_size)
{
    const float* x  = (const float*)d_in[0];
    const void*  ei = d_in[1];
    const float* W1 = (const float*)d_in[2];
    const float* b1 = (const float*)d_in[3];
    const float* W2 = (const float*)d_in[4];
    const float* b2 = (const float*)d_in[5];
    const float* W3 = (const float*)d_in[6];
    const float* b3 = (const float*)d_in[7];
    float* out = (float*)d_out;

    __half* hbuf = nullptr;
    float*  abuf = nullptr;
    float*  disb = nullptr;
    cudaGetSymbolAddress((void**)&hbuf, g_h);
    cudaGetSymbolAddress((void**)&abuf, g_a);
    cudaGetSymbolAddress((void**)&disb, g_dis);

    const int TPB = 256;
    int nb_nodes = (N_NODES + TPB - 1) / TPB;
    int nb_edges = (N_EDGES + TPB - 1) / TPB;

    // --- CSR build (6 launches) ---
    k_init<<<nb_nodes, TPB>>>((const int*)ei);
    k_prep<<<nb_edges, TPB>>>(ei);
    k_scanA<<<N_SCAN_BLOCKS, SCAN_BLK>>>();
    k_scanB<<<1, 128>>>();
    k_scanC<<<nb_nodes, TPB>>>();
    k_scatter<<<nb_edges, TPB>>>();

    int gemm_blocks = (N_NODES + 127) / 128;                 // 782
    int agg_blocks_128 = (N_NODES * 16 + TPB - 1) / TPB;     // GROUP=16
    int agg_blocks_64  = (N_NODES * 8  + TPB - 1) / TPB;     // GROUP=8

    // --- layer 1: h' = dis*(x @ W1) -> agg+relu -> a
    gemm_wmma<128, 64, 32><<<gemm_blocks, 256>>>(x, W1, hbuf, disb, N_NODES, IN_DIM);
    agg_kernel<128, 16, true><<<agg_blocks_128, 256>>>(hbuf, abuf, b1);

    // --- layer 2: h' = dis*(a @ W2) -> agg+relu -> a
    gemm_wmma<128, 64, 32><<<gemm_blocks, 256>>>(abuf, W2, hbuf, disb, N_NODES, HID_DIM);
    agg_kernel<128, 16, true><<<agg_blocks_128, 256>>>(hbuf, abuf, b2);

    // --- layer 3: h' = dis*(a @ W3) -> agg (no relu) -> d_out
    gemm_wmma<64, 32, 32><<<gemm_blocks, 256>>>(abuf, W3, hbuf, disb, N_NODES, HID_DIM);
    agg_kernel<64, 8, false><<<agg_blocks_64, 256>>>(hbuf, out, b3);
}

// round 13
// speedup vs baseline: 1.5395x; 1.0371x over previous
#include <cuda_runtime.h>
#include <cuda_fp16.h>
#include <mma.h>
#include <cstdint>
#include <type_traits>

using namespace nvcuda;

#define N_NODES 100000
#define N_EDGES 3200000
#define IN_DIM  256
#define HID_DIM 128
#define OUT_DIM 64
#define M_PAD   100096          // 782 * 128, so WMMA stores need no tail guard

#define SCAN_BLK 1024
#define N_SCAN_BLOCKS ((N_NODES + SCAN_BLK - 1) / SCAN_BLK)   // 98

// ---------------- device scratch (static: no runtime allocation) -------------
__device__ int    g_is64;
__device__ int    g_src[N_EDGES];
__device__ int    g_dst[N_EDGES];
__device__ int    g_ecnt[N_NODES];
__device__ float  g_dis[N_NODES];
__device__ int    g_rowptr[N_NODES + 1];
__device__ int    g_cur[N_NODES];
__device__ int    g_col[N_EDGES];
__device__ int    g_bsum[N_SCAN_BLOCKS];
__device__ int    g_bofs[N_SCAN_BLOCKS];
__device__ __half g_h[(size_t)M_PAD * HID_DIM];   // dis-scaled transform output, fp16
__device__ __half g_a[(size_t)M_PAD * HID_DIM];   // aggregation output (GEMM input), fp16

// ---------------- init: zero histogram + edge dtype detect --------------------
// int64 values < 2^17 -> every odd 32-bit word is 0; int32 -> odd words random.
__global__ void k_init(const int* __restrict__ ei32) {
    int i = blockIdx.x * blockDim.x + threadIdx.x;
    if (i < N_NODES) g_ecnt[i] = 0;
    if (blockIdx.x == 0) {
        __shared__ int nz;
        if (threadIdx.x == 0) nz = 0;
        __syncthreads();
        int idx = 2 * threadIdx.x + 1;
        if (threadIdx.x < 64 && ei32[idx] != 0) atomicAdd(&nz, 1);
        __syncthreads();
        if (threadIdx.x == 0) g_is64 = (nz == 0) ? 1 : 0;
    }
}

// fused: normalize edge dtype + in-degree histogram (one pass over edge_index)
__global__ void k_prep(const void* __restrict__ ei) {
    int e = blockIdx.x * blockDim.x + threadIdx.x;
    if (e >= N_EDGES) return;
    int s, d;
    if (g_is64) {
        const long long* p = (const long long*)ei;
        s = (int)p[e];
        d = (int)p[N_EDGES + e];
    } else {
        const int* p = (const int*)ei;
        s = p[e];
        d = p[N_EDGES + e];
    }
    g_src[e] = s;
    g_dst[e] = d;
    if ((unsigned)d < N_NODES) atomicAdd(&g_ecnt[d], 1);
}

// block-level exclusive scan (also emits dis = rsqrt(deg+1))
__global__ void k_scanA() {
    __shared__ int s[SCAN_BLK];
    int gid = blockIdx.x * SCAN_BLK + threadIdx.x;
    int v = (gid < N_NODES) ? g_ecnt[gid] : 0;
    if (gid < N_NODES) g_dis[gid] = rsqrtf((float)(v + 1));
    s[threadIdx.x] = v;
    __syncthreads();
    #pragma unroll
    for (int d = 1; d < SCAN_BLK; d <<= 1) {
        int t = (threadIdx.x >= d) ? s[threadIdx.x - d] : 0;
        __syncthreads();
        s[threadIdx.x] += t;
        __syncthreads();
    }
    if (gid < N_NODES) g_rowptr[gid] = s[threadIdx.x] - v;
    if (threadIdx.x == SCAN_BLK - 1) g_bsum[blockIdx.x] = s[SCAN_BLK - 1];
}

// scan of the 98 block partials: one block, shuffle scan
__global__ void k_scanB() {
    int t = threadIdx.x;                       // 0..127
    int lane = t & 31, w = t >> 5;
    int v = (t < N_SCAN_BLOCKS) ? g_bsum[t] : 0;
    int x = v;
    #pragma unroll
    for (int d = 1; d < 32; d <<= 1) {
        int y = __shfl_up_sync(0xFFFFFFFFu, x, d);
        if (lane >= d) x += y;
    }
    __shared__ int wsum[4];
    if (lane == 31) wsum[w] = x;
    __syncthreads();
    int offs = 0;
    #pragma unroll
    for (int i = 0; i < 4; i++) offs += (i < w) ? wsum[i] : 0;
    if (t < N_SCAN_BLOCKS) g_bofs[t] = offs + x - v;   // exclusive
}

__global__ void k_scanC() {
    int i = blockIdx.x * blockDim.x + threadIdx.x;
    if (i < N_NODES) {
        int r = g_rowptr[i] + g_bofs[i / SCAN_BLK];
        g_rowptr[i] = r;
        g_cur[i] = r;
    }
    if (i == 0) g_rowptr[N_NODES] = N_EDGES;
}

__global__ void k_scatter() {
    int e = blockIdx.x * blockDim.x + threadIdx.x;
    if (e < N_EDGES) {
        int src = g_src[e];
        int dst = g_dst[e];
        if ((unsigned)dst < N_NODES && (unsigned)src < N_NODES) {
            int pos = atomicAdd(&g_cur[dst], 1);
            g_col[pos] = src;
        }
    }
}

// ---------------- WMMA GEMM: C_half[r,:] = dis[r] * (A[r,:] @ B) --------------
// dis-scaling folded into the A staging. A is fp32 (layer 1, float4 loads) or
// fp16 (layers 2/3, uint4 = 8-half loads; 16B smem stores). fp32 accum,
// fp16 output. BM=128, BK=32, 256 threads = 8 warps.
template <int BN, int WM, int WN, typename TA>
__global__ __launch_bounds__(256) void gemm_wmma(
    const TA* __restrict__ A, const float* __restrict__ B,
    __half* __restrict__ C, const float* __restrict__ dis, int M, int K)
{
    constexpr int BM = 128, BK = 32, PAD = 8;
    constexpr int WARPS_M = BM / WM;
    constexpr int MT = WM / 16, NT = WN / 16;
    static_assert((BM / WM) * (BN / WN) == 8, "8 warps");

    __shared__ __half As[BM][BK + PAD];   // row stride 80B (16B-aligned)
    __shared__ __half Bs[BK][BN + PAD];

    int tid = threadIdx.x;
    int warpId = tid >> 5;
    int wm = warpId % WARPS_M;
    int wn = warpId / WARPS_M;
    int row0 = blockIdx.x * BM;

    wmma::fragment<wmma::accumulator, 16, 16, 16, float> cf[MT][NT];
    #pragma unroll
    for (int i = 0; i < MT; i++)
        #pragma unroll
        for (int j = 0; j < NT; j++) wmma::fill_fragment(cf[i][j], 0.0f);

    for (int kt = 0; kt < K; kt += BK) {
        if constexpr (std::is_same<TA, float>::value) {
            // stage A (fp32): 128 x 32, float4 loads, dis-scaled fp16 stores
            #pragma unroll
            for (int i = tid; i < BM * BK / 4; i += 256) {
                int r  = i >> 3;
                int c4 = (i & 7) << 2;
                float4 v = make_float4(0.f, 0.f, 0.f, 0.f);
                int grow = row0 + r;
                if (grow < M) {
                    v = *(const float4*)&A[(size_t)grow * K + kt + c4];
                    float w = __ldg(&dis[grow]);
                    v.x *= w; v.y *= w; v.z *= w; v.w *= w;
                }
                As[r][c4 + 0] = __float2half_rn(v.x);
                As[r][c4 + 1] = __float2half_rn(v.y);
                As[r][c4 + 2] = __float2half_rn(v.z);
                As[r][c4 + 3] = __float2half_rn(v.w);
            }
        } else {
            // stage A (fp16): 128 x 32, uint4 loads (8 halves = 16B), 16B stores
            #pragma unroll
            for (int i = tid; i < BM * BK / 8; i += 256) {   // 512 iters total
                int r  = i >> 2;           // 4 uint4 per row
                int c8 = (i & 3) << 3;
                uint4 raw = make_uint4(0u, 0u, 0u, 0u);
                float w = 0.f;
                int grow = row0 + r;
                if (grow < M) {
                    raw = *(const uint4*)&A[(size_t)grow * K + kt + c8];
                    w = __ldg(&dis[grow]);
                }
                float2 u0 = __half22float2(*(__half2*)&raw.x);
                float2 u1 = __half22float2(*(__half2*)&raw.y);
                float2 u2 = __half22float2(*(__half2*)&raw.z);
                float2 u3 = __half22float2(*(__half2*)&raw.w);
                uint4 outv;
                *(__half2*)&outv.x = __floats2half2_rn(u0.x * w, u0.y * w);
                *(__half2*)&outv.y = __floats2half2_rn(u1.x * w, u1.y * w);
                *(__half2*)&outv.z = __floats2half2_rn(u2.x * w, u2.y * w);
                *(__half2*)&outv.w = __floats2half2_rn(u3.x * w, u3.y * w);
                *(uint4*)&As[r][c8] = outv;
            }
        }
        // stage B: 32 x BN fp32 -> fp16 smem
        #pragma unroll
        for (int i = tid; i < BK * BN / 4; i += 256) {
            int r  = i / (BN / 4);
            int c4 = (i % (BN / 4)) << 2;
            float4 v = *(const float4*)&B[(size_t)(kt + r) * BN + c4];
            Bs[r][c4 + 0] = __float2half_rn(v.x);
            Bs[r][c4 + 1] = __float2half_rn(v.y);
            Bs[r][c4 + 2] = __float2half_rn(v.z);
            Bs[r][c4 + 3] = __float2half_rn(v.w);
        }
        __syncthreads();

        #pragma unroll
        for (int kk = 0; kk < BK; kk += 16) {
            wmma::fragment<wmma::matrix_a, 16, 16, 16, __half, wmma::row_major> af[MT];
            wmma::fragment<wmma::matrix_b, 16, 16, 16, __half, wmma::row_major> bf[NT];
            #pragma unroll
            for (int i = 0; i < MT; i++)
                wmma::load_matrix_sync(af[i], &As[wm * WM + i * 16][kk], BK + PAD);
            #pragma unroll
            for (int j = 0; j < NT; j++)
                wmma::load_matrix_sync(bf[j], &Bs[kk][wn * WN + j * 16], BN + PAD);
            #pragma unroll
            for (int i = 0; i < MT; i++)
                #pragma unroll
                for (int j = 0; j < NT; j++)
                    wmma::mma_sync(cf[i][j], af[i], bf[j], cf[i][j]);
        }
        __syncthreads();
    }

    #pragma unroll
    for (int i = 0; i < MT; i++) {
        #pragma unroll
        for (int j = 0; j < NT; j++) {
            wmma::fragment<wmma::accumulator, 16, 16, 16, __half> hf;
            #pragma unroll
            for (int e = 0; e < cf[i][j].num_elements; e++)
                hf.x[e] = __float2half_rn(cf[i][j].x[e]);
            __half* dst = C + (size_t)(row0 + wm * WM + i * 16) * BN + wn * WN + j * 16;
            wmma::store_matrix_sync(dst, hf, BN, wmma::mem_row_major);
        }
    }
}

// ---------------- aggregation --------------------------------------------------
// h' rows are pre-scaled by dis[src]. out[i] = dis[i]*(h'_i + sum_j h'_j) + b.
// GROUP lanes per dst node; each lane owns 8 fp16 features = ONE 16B LDG.128
// per gathered row. GROUP=16 for F=128 (2 nodes/warp), GROUP=8 for F=64.
// TOUT=__half for intermediate layers (16B stores), float for d_out.
__device__ __forceinline__ void h8_acc(uint4 raw, float* f) {
    float2 u0 = __half22float2(*(__half2*)&raw.x);
    float2 u1 = __half22float2(*(__half2*)&raw.y);
    float2 u2 = __half22float2(*(__half2*)&raw.z);
    float2 u3 = __half22float2(*(__half2*)&raw.w);
    f[0] += u0.x; f[1] += u0.y; f[2] += u1.x; f[3] += u1.y;
    f[4] += u2.x; f[5] += u2.y; f[6] += u3.x; f[7] += u3.y;
}

template <int F, int GROUP, bool RELU, typename TOUT>
__global__ __launch_bounds__(256) void agg_kernel(
    const __half* __restrict__ h, TOUT* __restrict__ out,
    const float* __restrict__ bias)
{
    static_assert(F == GROUP * 8, "lane owns 8 features (16B)");
    constexpr int ROWU4 = F / 8;          // uint4 per row
    int gtid = blockIdx.x * blockDim.x + threadIdx.x;
    int node = gtid / GROUP;
    int lane = gtid % GROUP;
    if (node >= N_NODES) return;

    const uint4* h4 = (const uint4*)h;

    float acc[8] = {0.f, 0.f, 0.f, 0.f, 0.f, 0.f, 0.f, 0.f};
    // self term (h' already dis-scaled)
    h8_acc(__ldg(&h4[(size_t)node * ROWU4 + lane]), acc);

    int p   = g_rowptr[node];
    int end = g_rowptr[node + 1];

    for (; p + 4 <= end; p += 4) {
        int j0 = __ldg(&g_col[p + 0]);
        int j1 = __ldg(&g_col[p + 1]);
        int j2 = __ldg(&g_col[p + 2]);
        int j3 = __ldg(&g_col[p + 3]);
        uint4 r0 = __ldg(&h4[(size_t)j0 * ROWU4 + lane]);
        uint4 r1 = __ldg(&h4[(size_t)j1 * ROWU4 + lane]);
        uint4 r2 = __ldg(&h4[(size_t)j2 * ROWU4 + lane]);
        uint4 r3 = __ldg(&h4[(size_t)j3 * ROWU4 + lane]);
        h8_acc(r0, acc);
        h8_acc(r1, acc);
        h8_acc(r2, acc);
        h8_acc(r3, acc);
    }
    for (; p < end; p++) {
        int j = __ldg(&g_col[p]);
        h8_acc(__ldg(&h4[(size_t)j * ROWU4 + lane]), acc);
    }

    float di = __ldg(&g_dis[node]);
    float4 bA = *(const float4*)&bias[lane * 8 + 0];
    float4 bB = *(const float4*)&bias[lane * 8 + 4];
    float o[8];
    o[0] = di * acc[0] + bA.x; o[1] = di * acc[1] + bA.y;
    o[2] = di * acc[2] + bA.z; o[3] = di * acc[3] + bA.w;
    o[4] = di * acc[4] + bB.x; o[5] = di * acc[5] + bB.y;
    o[6] = di * acc[6] + bB.z; o[7] = di * acc[7] + bB.w;
    if (RELU) {
        #pragma unroll
        for (int i = 0; i < 8; i++) o[i] = fmaxf(o[i], 0.f);
    }
    if constexpr (std::is_same<TOUT, float>::value) {
        float* orow = &out[(size_t)node * F + lane * 8];
        *(float4*)&orow[0] = make_float4(o[0], o[1], o[2], o[3]);
        *(float4*)&orow[4] = make_float4(o[4], o[5], o[6], o[7]);
    } else {
        uint4 packed;
        *(__half2*)&packed.x = __floats2half2_rn(o[0], o[1]);
        *(__half2*)&packed.y = __floats2half2_rn(o[2], o[3]);
        *(__half2*)&packed.z = __floats2half2_rn(o[4], o[5]);
        *(__half2*)&packed.w = __floats2half2_rn(o[6], o[7]);
        *(uint4*)&out[(size_t)node * F + lane * 8] = packed;
    }
}

// ---------------- launch ------------------------------------------------------
extern "C" void kernel_launch(void* const* d_in, const int* in_sizes, int n_in,
                              void* d_out, int out_size)
{
    const float* x  = (const float*)d_in[0];
    const void*  ei = d_in[1];
    const float* W1 = (const float*)d_in[2];
    const float* b1 = (const float*)d_in[3];
    const float* W2 = (const float*)d_in[4];
    const float* b2 = (const float*)d_in[5];
    const float* W3 = (const float*)d_in[6];
    const float* b3 = (const float*)d_in[7];
    float* out = (float*)d_out;

    __half* hbuf = nullptr;
    __half* abuf = nullptr;
    float*  disb = nullptr;
    cudaGetSymbolAddress((void**)&hbuf, g_h);
    cudaGetSymbolAddress((void**)&abuf, g_a);
    cudaGetSymbolAddress((void**)&disb, g_dis);

    const int TPB = 256;
    int nb_nodes = (N_NODES + TPB - 1) / TPB;
    int nb_edges = (N_EDGES + TPB - 1) / TPB;

    // --- CSR build (6 launches) ---
    k_init<<<nb_nodes, TPB>>>((const int*)ei);
    k_prep<<<nb_edges, TPB>>>(ei);
    k_scanA<<<N_SCAN_BLOCKS, SCAN_BLK>>>();
    k_scanB<<<1, 128>>>();
    k_scanC<<<nb_nodes, TPB>>>();
    k_scatter<<<nb_edges, TPB>>>();

    int gemm_blocks = (N_NODES + 127) / 128;                 // 782
    int agg_blocks_128 = (N_NODES * 16 + TPB - 1) / TPB;     // GROUP=16
    int agg_blocks_64  = (N_NODES * 8  + TPB - 1) / TPB;     // GROUP=8

    // --- layer 1: h' = dis*(x @ W1) -> agg+relu -> a (fp16)
    gemm_wmma<128, 64, 32, float><<<gemm_blocks, 256>>>(x, W1, hbuf, disb, N_NODES, IN_DIM);
    agg_kernel<128, 16, true, __half><<<agg_blocks_128, 256>>>(hbuf, abuf, b1);

    // --- layer 2: h' = dis*(a @ W2) -> agg+relu -> a (fp16)
    gemm_wmma<128, 64, 32, __half><<<gemm_blocks, 256>>>(abuf, W2, hbuf, disb, N_NODES, HID_DIM);
    agg_kernel<128, 16, true, __half><<<agg_blocks_128, 256>>>(hbuf, abuf, b2);

    // --- layer 3: h' = dis*(a @ W3) -> agg (no relu) -> d_out (fp32)
    gemm_wmma<64, 32, 32, __half><<<gemm_blocks, 256>>>(abuf, W3, hbuf, disb, N_NODES, HID_DIM);
    agg_kernel<64, 8, false, float><<<agg_blocks_64, 256>>>(hbuf, out, b3);
}